// round 6
// baseline (speedup 1.0000x reference)
#include <cuda_runtime.h>
#include <cuda_bf16.h>
#include <math.h>
#include <stdint.h>

// Problem constants
#define B_    64
#define T_    2048
#define ENC_  512
#define DEC_  1024
#define HID_  256
#define KCONV 31
#define PADC  15

// Tiling: CTA = 128 (bt) x 128 (h), K-chunk 64, double-buffered smem
// stage layout (bytes): A_f32[128][72 floats] | Whi[128][72 bf16] | Wlo[128][72 bf16]
#define AF32  0
#define LDAF  72                  // fp32 row stride (288 B) -> conflict-free float2 frags
#define W_HI  36864
#define W_LO  55296
#define WROWB 144                 // bf16 W row stride bytes
#define STAGE_B 73728
#define ESMEM (2 * STAGE_B)       // 147456

// ---------------- device scratch ----------------
__device__ __nv_bfloat16 g_Whi[HID_ * ENC_];
__device__ __nv_bfloat16 g_Wlo[HID_ * ENC_];
__device__ __nv_bfloat16 g_F[HID_ * 32];        // fused conv filter, col 31 = 0
__device__ float g_dec[B_ * HID_];              // dec projection + b_enc
__device__ float g_epart[2][B_ * T_];           // energy partials per n-half
__device__ float g_part[B_ * 16 * ENC_];        // att_c partials (16 t-slices)

// ---------------- PTX helpers ----------------
__device__ __forceinline__ void cp16(uint32_t dst, const void* src) {
    asm volatile("cp.async.cg.shared.global [%0], [%1], 16;\n" :: "r"(dst), "l"(src));
}
#define CP_COMMIT() asm volatile("cp.async.commit_group;\n" ::: "memory")
#define CP_WAIT0()  asm volatile("cp.async.wait_group 0;\n" ::: "memory")

__device__ __forceinline__ void ldsm_x4(uint32_t (&r)[4], uint32_t addr) {
    asm volatile("ldmatrix.sync.aligned.m8n8.x4.shared.b16 {%0,%1,%2,%3}, [%4];"
                 : "=r"(r[0]), "=r"(r[1]), "=r"(r[2]), "=r"(r[3]) : "r"(addr));
}

__device__ __forceinline__ void mma_bf16(float& c0, float& c1, float& c2, float& c3,
                                         uint32_t a0, uint32_t a1, uint32_t a2, uint32_t a3,
                                         uint32_t b0, uint32_t b1) {
    asm volatile(
        "mma.sync.aligned.m16n8k16.row.col.f32.bf16.bf16.f32 "
        "{%0,%1,%2,%3}, {%4,%5,%6,%7}, {%8,%9}, {%0,%1,%2,%3};"
        : "+f"(c0), "+f"(c1), "+f"(c2), "+f"(c3)
        : "r"(a0), "r"(a1), "r"(a2), "r"(a3), "r"(b0), "r"(b1));
}

// fp32 pair -> bf16 hi pair + residual lo pair
__device__ __forceinline__ void cvt2(float x, float y, uint32_t& hi, uint32_t& lo) {
    __nv_bfloat16 h0 = __float2bfloat16(x);
    __nv_bfloat16 h1 = __float2bfloat16(y);
    __nv_bfloat162 hp; hp.x = h0; hp.y = h1;
    __nv_bfloat162 lp = __floats2bfloat162_rn(x - __bfloat162float(h0),
                                              y - __bfloat162float(h1));
    hi = *(uint32_t*)&hp;
    lo = *(uint32_t*)&lp;
}

// ---------------- merged prep kernel ----------------
__global__ void prep_all(const float* __restrict__ W_enc,
                         const float* __restrict__ W_att,
                         const float* __restrict__ conv_w,
                         const float* __restrict__ dec_state,
                         const float* __restrict__ W_dec,
                         const float* __restrict__ b_enc) {
    int bx = blockIdx.x, tid = threadIdx.x;
    if (bx < 512) {
        int i = bx * 256 + tid;
        float x = W_enc[i];
        __nv_bfloat16 h = __float2bfloat16(x);
        g_Whi[i] = h;
        g_Wlo[i] = __float2bfloat16(x - __bfloat162float(h));
    } else if (bx < 544) {
        int i = (bx - 512) * 256 + tid;
        int h = i >> 5, k = i & 31;
        float s = 0.f;
        if (k < KCONV) {
            #pragma unroll
            for (int c = 0; c < 32; c++) s += W_att[h * 32 + c] * conv_w[c * KCONV + k];
        }
        g_F[i] = __float2bfloat16(s);
    } else {
        int wid_g = (bx - 544) * 8 + (tid >> 5);
        int lane = tid & 31;
        int b = wid_g >> 8, h = wid_g & 255;
        const float4* d = (const float4*)(dec_state + (size_t)b * DEC_);
        const float4* w = (const float4*)(W_dec + (size_t)h * DEC_);
        float s = 0.f;
        #pragma unroll
        for (int it = 0; it < 8; it++) {
            float4 dv = d[lane + it * 32];
            float4 wv = w[lane + it * 32];
            s += dv.x * wv.x + dv.y * wv.y + dv.z * wv.z + dv.w * wv.w;
        }
        #pragma unroll
        for (int off = 16; off > 0; off >>= 1) s += __shfl_xor_sync(0xffffffffu, s, off);
        if (lane == 0) g_dec[wid_g] = s + b_enc[h];
    }
}

// ---------------- energy kernel ----------------
__global__ void __launch_bounds__(256)
energy_kernel(const float* __restrict__ enc,
              const float* __restrict__ prev,
              const float* __restrict__ w_w) {
    extern __shared__ char sm[];
    uint32_t smb;
    asm("{ .reg .u64 t; cvta.to.shared.u64 t, %1; cvt.u32.u64 %0, t; }"
        : "=r"(smb) : "l"(sm));

    const int tid  = threadIdx.x;
    const int lane = tid & 31;
    const int warp = tid >> 5;
    const int wm   = warp & 3;     // 0..3 -> rows [wm*32, +32)
    const int wn   = warp >> 2;    // 0..1 -> cols [wn*64, +64)

    const int ny   = blockIdx.x & 1;          // which n-half of HID
    const int m0   = (blockIdx.x >> 1) * 128;
    const int b    = m0 >> 11;
    const int t0   = m0 & (T_ - 1);

    const int prow = tid >> 1;     // producer row (0..127)
    const int phal = tid & 1;      // producer half

    float acc[2][8][4];
    #pragma unroll
    for (int mi = 0; mi < 2; mi++)
        #pragma unroll
        for (int ni = 0; ni < 8; ni++)
            #pragma unroll
            for (int q = 0; q < 4; q++) acc[mi][ni][q] = 0.f;

    const float* arow = enc + ((size_t)b * T_ + t0 + prow) * ENC_;
    const __nv_bfloat16* wsrc_h = g_Whi + (size_t)(ny * 128 + prow) * ENC_;
    const __nv_bfloat16* wsrc_l = g_Wlo + (size_t)(ny * 128 + prow) * ENC_;

    // fragment addressing constants
    const int g  = lane >> 2, tq = lane & 3;
    const int b_row = (lane & 7) + ((lane >> 4) & 1) * 8;
    const int b_col = ((lane >> 3) & 1) * 8;

    auto produce_gemm = [&](int s, int kc) {
        uint32_t wa = smb + s * STAGE_B;
        // A fp32: 128 rows x 64 floats; this thread: 8x16B at row, half*128B
        uint32_t da = wa + AF32 + prow * (LDAF * 4) + phal * 128;
        const float* sa = arow + kc + phal * 32;
        #pragma unroll
        for (int j = 0; j < 8; j++) cp16(da + j * 16, sa + j * 4);
        // W hi/lo: 128 rows x 64 bf16; this thread: 4+4 x16B
        uint32_t dh = wa + W_HI + prow * WROWB + phal * 64;
        uint32_t dl = wa + W_LO + prow * WROWB + phal * 64;
        #pragma unroll
        for (int j = 0; j < 4; j++) {
            cp16(dh + j * 16, wsrc_h + kc + phal * 32 + j * 8);
            cp16(dl + j * 16, wsrc_l + kc + phal * 32 + j * 8);
        }
    };

    auto produce_conv = [&](int s) {
        uint32_t wa = smb + s * STAGE_B;
        // F: 128 rows x 32 bf16 (64B/row): 2 cp16 per thread
        uint32_t dh = wa + W_HI + prow * WROWB + phal * 32;
        cp16(dh,      g_F + (ny * 128 + prow) * 32 + phal * 16);
        cp16(dh + 16, g_F + (ny * 128 + prow) * 32 + phal * 16 + 8);
        // shifted prev fp32: 128 rows x 32 floats; thread: row=tid>>1, half -> 16 floats
        float* Af = (float*)(sm + s * STAGE_B + AF32) + prow * LDAF + phal * 16;
        #pragma unroll
        for (int q = 0; q < 4; q++) {
            float4 v;
            #pragma unroll
            for (int e = 0; e < 4; e++) {
                int k = phal * 16 + q * 4 + e;
                int t = t0 + prow - PADC + k;
                float pv = (k < KCONV && t >= 0 && t < T_) ? prev[b * T_ + t] : 0.f;
                ((float*)&v)[e] = pv;
            }
            *(float4*)(Af + q * 4) = v;
        }
    };

    auto consume = [&](int s, int ksteps, bool do_wlo) {
        const uint32_t stg = smb + s * STAGE_B;
        const float* Af = (const float*)(sm + s * STAGE_B + AF32);
        for (int ks = 0; ks < ksteps; ks++) {
            const int kb = ks * 16;
            uint32_t ahi[2][4], alo[2][4];
            #pragma unroll
            for (int mi = 0; mi < 2; mi++) {
                const float* ap = Af + (wm * 32 + mi * 16 + g) * LDAF + kb + 2 * tq;
                float2 f0 = *(const float2*)(ap);
                float2 f1 = *(const float2*)(ap + 8 * LDAF);
                float2 f2 = *(const float2*)(ap + 8);
                float2 f3 = *(const float2*)(ap + 8 * LDAF + 8);
                cvt2(f0.x, f0.y, ahi[mi][0], alo[mi][0]);
                cvt2(f1.x, f1.y, ahi[mi][1], alo[mi][1]);
                cvt2(f2.x, f2.y, ahi[mi][2], alo[mi][2]);
                cvt2(f3.x, f3.y, ahi[mi][3], alo[mi][3]);
            }
            uint32_t wf[4][4];
            #pragma unroll
            for (int p = 0; p < 4; p++) {
                ldsm_x4(wf[p], stg + W_HI + (wn * 64 + p * 16 + b_row) * WROWB
                               + (kb + b_col) * 2);
            }
            #pragma unroll
            for (int p = 0; p < 4; p++)
                #pragma unroll
                for (int mi = 0; mi < 2; mi++) {
                    mma_bf16(acc[mi][2*p][0], acc[mi][2*p][1], acc[mi][2*p][2], acc[mi][2*p][3],
                             ahi[mi][0], ahi[mi][1], ahi[mi][2], ahi[mi][3],
                             wf[p][0], wf[p][1]);
                    mma_bf16(acc[mi][2*p+1][0], acc[mi][2*p+1][1], acc[mi][2*p+1][2], acc[mi][2*p+1][3],
                             ahi[mi][0], ahi[mi][1], ahi[mi][2], ahi[mi][3],
                             wf[p][2], wf[p][3]);
                }
            #pragma unroll
            for (int p = 0; p < 4; p++)
                #pragma unroll
                for (int mi = 0; mi < 2; mi++) {
                    mma_bf16(acc[mi][2*p][0], acc[mi][2*p][1], acc[mi][2*p][2], acc[mi][2*p][3],
                             alo[mi][0], alo[mi][1], alo[mi][2], alo[mi][3],
                             wf[p][0], wf[p][1]);
                    mma_bf16(acc[mi][2*p+1][0], acc[mi][2*p+1][1], acc[mi][2*p+1][2], acc[mi][2*p+1][3],
                             alo[mi][0], alo[mi][1], alo[mi][2], alo[mi][3],
                             wf[p][2], wf[p][3]);
                }
            if (do_wlo) {
                #pragma unroll
                for (int p = 0; p < 4; p++) {
                    ldsm_x4(wf[p], stg + W_LO + (wn * 64 + p * 16 + b_row) * WROWB
                                   + (kb + b_col) * 2);
                }
                #pragma unroll
                for (int p = 0; p < 4; p++)
                    #pragma unroll
                    for (int mi = 0; mi < 2; mi++) {
                        mma_bf16(acc[mi][2*p][0], acc[mi][2*p][1], acc[mi][2*p][2], acc[mi][2*p][3],
                                 ahi[mi][0], ahi[mi][1], ahi[mi][2], ahi[mi][3],
                                 wf[p][0], wf[p][1]);
                        mma_bf16(acc[mi][2*p+1][0], acc[mi][2*p+1][1], acc[mi][2*p+1][2], acc[mi][2*p+1][3],
                                 ahi[mi][0], ahi[mi][1], ahi[mi][2], ahi[mi][3],
                                 wf[p][2], wf[p][3]);
                    }
            }
        }
    };

    // ---- prologue ----
    produce_gemm(0, 0);
    CP_COMMIT();
    CP_WAIT0();
    __syncthreads();

    // ---- main loop: chunks 0..7 = GEMM, chunk 8 = conv ----
    for (int c = 0; c <= 8; c++) {
        const int cur = c & 1, nxt = cur ^ 1;
        if (c < 8) {
            if (c < 7) produce_gemm(nxt, (c + 1) * 64);
            else       produce_conv(nxt);
            CP_COMMIT();
        }
        if (c < 8) consume(cur, 4, true);
        else       consume(cur, 2, false);
        if (c < 8) CP_WAIT0();
        __syncthreads();
    }

    // ---- epilogue: partial energy over this CTA's 128 h-cols ----
    float* red = (float*)sm;   // 128 x 2 floats (aliases stage0, post-sync)
    float wv[16], dv[16];
    {
        int cbase = ny * 128 + wn * 64 + tq * 2;
        #pragma unroll
        for (int ni = 0; ni < 8; ni++) {
            int n = cbase + ni * 8;
            wv[2 * ni]     = w_w[n];
            wv[2 * ni + 1] = w_w[n + 1];
            dv[2 * ni]     = g_dec[b * HID_ + n];
            dv[2 * ni + 1] = g_dec[b * HID_ + n + 1];
        }
    }
    #pragma unroll
    for (int mi = 0; mi < 2; mi++) {
        #pragma unroll
        for (int h2 = 0; h2 < 2; h2++) {
            float p = 0.f;
            #pragma unroll
            for (int ni = 0; ni < 8; ni++) {
                #pragma unroll
                for (int j = 0; j < 2; j++) {
                    float s = acc[mi][ni][h2 * 2 + j] + dv[2 * ni + j];
                    p += wv[2 * ni + j] * tanhf(s);
                }
            }
            p += __shfl_xor_sync(0xffffffffu, p, 1);
            p += __shfl_xor_sync(0xffffffffu, p, 2);
            if (tq == 0) {
                int row = wm * 32 + mi * 16 + h2 * 8 + g;
                red[row * 2 + wn] = p;
            }
        }
    }
    __syncthreads();
    if (tid < 128) {
        g_epart[ny][m0 + tid] = red[tid * 2] + red[tid * 2 + 1];
    }
}

// ---------------- masked softmax over T (sums the two energy partials) ----------------
__global__ void softmax_kernel(const int* __restrict__ text_len, float* __restrict__ out) {
    __shared__ float sh[T_];
    __shared__ float rbuf[256];
    int b = blockIdx.x, tid = threadIdx.x;
    int len = text_len[b];

    float mx = -INFINITY;
    for (int t = tid; t < T_; t += 256) {
        float v = (t < len) ? (g_epart[0][b * T_ + t] + g_epart[1][b * T_ + t]) : -INFINITY;
        sh[t] = v;
        mx = fmaxf(mx, v);
    }
    rbuf[tid] = mx; __syncthreads();
    for (int s = 128; s > 0; s >>= 1) {
        if (tid < s) rbuf[tid] = fmaxf(rbuf[tid], rbuf[tid + s]);
        __syncthreads();
    }
    mx = rbuf[0];
    __syncthreads();

    float sum = 0.f;
    for (int t = tid; t < T_; t += 256) {
        float v = sh[t];
        float e = (v == -INFINITY) ? 0.f : expf(v - mx);
        sh[t] = e;
        sum += e;
    }
    rbuf[tid] = sum; __syncthreads();
    for (int s = 128; s > 0; s >>= 1) {
        if (tid < s) rbuf[tid] += rbuf[tid + s];
        __syncthreads();
    }
    float inv = 1.f / rbuf[0];

    float* attw = out + B_ * ENC_;
    for (int t = tid; t < T_; t += 256)
        attw[b * T_ + t] = sh[t] * inv;
}

// ---------------- att_c = sum_t att_w[b,t] * enc[b,t,:]  (16 t-slices) ----------------
__global__ void attc_part(const float* __restrict__ enc, const float* __restrict__ attw) {
    __shared__ float w[128];
    int ts = blockIdx.x;
    int b  = blockIdx.y;
    int tid = threadIdx.x;  // 128
    w[tid] = attw[b * T_ + ts * 128 + tid];
    __syncthreads();

    const float4* e4 = (const float4*)(enc + ((size_t)b * T_ + ts * 128) * ENC_) + tid;
    float ax = 0.f, ay = 0.f, az = 0.f, aw = 0.f;
    #pragma unroll 8
    for (int tt = 0; tt < 128; tt++) {
        float4 v = e4[(size_t)tt * (ENC_ / 4)];
        float ww = w[tt];
        ax += ww * v.x; ay += ww * v.y; az += ww * v.z; aw += ww * v.w;
    }
    float4 rr; rr.x = ax; rr.y = ay; rr.z = az; rr.w = aw;
    *(float4*)&g_part[((b * 16 + ts) * ENC_) + tid * 4] = rr;
}

__global__ void attc_reduce(float* __restrict__ out) {
    int i = blockIdx.x * 256 + threadIdx.x;
    if (i < B_ * ENC_) {
        int b = i >> 9, c = i & (ENC_ - 1);
        float s = 0.f;
        #pragma unroll
        for (int ts = 0; ts < 16; ts++) s += g_part[(b * 16 + ts) * ENC_ + c];
        out[i] = s;
    }
}

// ---------------- launch ----------------
extern "C" void kernel_launch(void* const* d_in, const int* in_sizes, int n_in,
                              void* d_out, int out_size) {
    const float* enc       = (const float*)d_in[0];
    const float* dec_state = (const float*)d_in[1];
    const float* prev      = (const float*)d_in[2];
    const int*   text_len  = (const int*)d_in[3];
    const float* W_enc     = (const float*)d_in[4];
    const float* b_enc     = (const float*)d_in[5];
    const float* W_dec     = (const float*)d_in[6];
    const float* W_att     = (const float*)d_in[7];
    const float* conv_w    = (const float*)d_in[8];
    const float* w_w       = (const float*)d_in[9];
    // d_in[10] = w_b: additive constant cancels in softmax.
    float* out = (float*)d_out;

    cudaFuncSetAttribute(energy_kernel, cudaFuncAttributeMaxDynamicSharedMemorySize, ESMEM);

    prep_all<<<2592, 256>>>(W_enc, W_att, conv_w, dec_state, W_dec, b_enc);

    energy_kernel<<<(B_ * T_ / 128) * 2, 256, ESMEM>>>(enc, prev, w_w);

    softmax_kernel<<<B_, 256>>>(text_len, out);

    attc_part<<<dim3(16, B_), 128>>>(enc, out + B_ * ENC_);
    attc_reduce<<<(B_ * ENC_ + 255) / 256, 256>>>(out);
}

// round 7
// speedup vs baseline: 1.2869x; 1.2869x over previous
#include <cuda_runtime.h>
#include <cuda_bf16.h>
#include <math.h>
#include <stdint.h>

// Problem constants
#define B_    64
#define T_    2048
#define ENC_  512
#define DEC_  1024
#define HID_  256
#define KCONV 31
#define PADC  15

// Tiling: CTA = 128 (bt) x 256 (h), 512 threads, K-chunk 64, double-buffered
// stage (bytes): Ahi[128*144] Alo[128*144] Whi[256*144] Wlo[256*144]
#define A_HI  0
#define A_LO  18432
#define W_HI  36864
#define W_LO  73728
#define ROWB  144                 // 72 bf16 per row (64 + 8 pad)
#define STAGE_B 110592
#define ESMEM (2 * STAGE_B)       // 221184

// ---------------- device scratch ----------------
__device__ __nv_bfloat16 g_Whi[HID_ * ENC_];
__device__ __nv_bfloat16 g_Wlo[HID_ * ENC_];
__device__ __nv_bfloat16 g_F[HID_ * 32];        // fused conv filter, col 31 = 0
__device__ float g_dec[B_ * HID_];              // dec projection + b_enc
__device__ float g_energy[B_ * T_];
__device__ float g_part[B_ * 16 * ENC_];        // att_c partials (16 t-slices)

// ---------------- PTX helpers ----------------
__device__ __forceinline__ void cp16(uint32_t dst, const void* src) {
    asm volatile("cp.async.cg.shared.global [%0], [%1], 16;\n" :: "r"(dst), "l"(src));
}
#define CP_COMMIT() asm volatile("cp.async.commit_group;\n" ::: "memory")
#define CP_WAIT0()  asm volatile("cp.async.wait_group 0;\n" ::: "memory")

__device__ __forceinline__ void ldsm_x4(uint32_t (&r)[4], uint32_t addr) {
    asm volatile("ldmatrix.sync.aligned.m8n8.x4.shared.b16 {%0,%1,%2,%3}, [%4];"
                 : "=r"(r[0]), "=r"(r[1]), "=r"(r[2]), "=r"(r[3]) : "r"(addr));
}

__device__ __forceinline__ void mma_bf16(float& c0, float& c1, float& c2, float& c3,
                                         uint32_t a0, uint32_t a1, uint32_t a2, uint32_t a3,
                                         uint32_t b0, uint32_t b1) {
    asm volatile(
        "mma.sync.aligned.m16n8k16.row.col.f32.bf16.bf16.f32 "
        "{%0,%1,%2,%3}, {%4,%5,%6,%7}, {%8,%9}, {%0,%1,%2,%3};"
        : "+f"(c0), "+f"(c1), "+f"(c2), "+f"(c3)
        : "r"(a0), "r"(a1), "r"(a2), "r"(a3), "r"(b0), "r"(b1));
}

// fp32 pair -> bf16 hi pair + residual lo pair
__device__ __forceinline__ void cvt2(float x, float y, uint32_t& hi, uint32_t& lo) {
    __nv_bfloat16 h0 = __float2bfloat16(x);
    __nv_bfloat16 h1 = __float2bfloat16(y);
    __nv_bfloat162 hp; hp.x = h0; hp.y = h1;
    __nv_bfloat162 lp = __floats2bfloat162_rn(x - __bfloat162float(h0),
                                              y - __bfloat162float(h1));
    hi = *(uint32_t*)&hp;
    lo = *(uint32_t*)&lp;
}

// ---------------- merged prep kernel ----------------
__global__ void prep_all(const float* __restrict__ W_enc,
                         const float* __restrict__ W_att,
                         const float* __restrict__ conv_w,
                         const float* __restrict__ dec_state,
                         const float* __restrict__ W_dec,
                         const float* __restrict__ b_enc) {
    int bx = blockIdx.x, tid = threadIdx.x;
    if (bx < 512) {
        int i = bx * 256 + tid;
        float x = W_enc[i];
        __nv_bfloat16 h = __float2bfloat16(x);
        g_Whi[i] = h;
        g_Wlo[i] = __float2bfloat16(x - __bfloat162float(h));
    } else if (bx < 544) {
        int i = (bx - 512) * 256 + tid;
        int h = i >> 5, k = i & 31;
        float s = 0.f;
        if (k < KCONV) {
            #pragma unroll
            for (int c = 0; c < 32; c++) s += W_att[h * 32 + c] * conv_w[c * KCONV + k];
        }
        g_F[i] = __float2bfloat16(s);
    } else {
        int wid_g = (bx - 544) * 8 + (tid >> 5);
        int lane = tid & 31;
        int b = wid_g >> 8, h = wid_g & 255;
        const float4* d = (const float4*)(dec_state + (size_t)b * DEC_);
        const float4* w = (const float4*)(W_dec + (size_t)h * DEC_);
        float s = 0.f;
        #pragma unroll
        for (int it = 0; it < 8; it++) {
            float4 dv = d[lane + it * 32];
            float4 wv = w[lane + it * 32];
            s += dv.x * wv.x + dv.y * wv.y + dv.z * wv.z + dv.w * wv.w;
        }
        #pragma unroll
        for (int off = 16; off > 0; off >>= 1) s += __shfl_xor_sync(0xffffffffu, s, off);
        if (lane == 0) g_dec[wid_g] = s + b_enc[h];
    }
}

// ---------------- energy kernel: 512 threads, producer-side conversion ----------------
__global__ void __launch_bounds__(512)
energy_kernel(const float* __restrict__ enc,
              const float* __restrict__ prev,
              const float* __restrict__ w_w) {
    extern __shared__ char sm[];
    uint32_t smb;
    asm("{ .reg .u64 t; cvta.to.shared.u64 t, %1; cvt.u32.u64 %0, t; }"
        : "=r"(smb) : "l"(sm));

    const int tid  = threadIdx.x;
    const int lane = tid & 31;
    const int warp = tid >> 5;
    const int wm   = warp & 3;     // rows [wm*32, +32)
    const int wn   = warp >> 2;    // cols [wn*64, +64)

    const int m0 = blockIdx.x * 128;
    const int b  = m0 >> 11;
    const int t0 = m0 & (T_ - 1);

    // producer roles
    const int arow  = tid >> 2;    // 0..127 (A row)
    const int aq    = tid & 3;     // 16-col group
    const int wrow  = tid >> 1;    // 0..255 (W row)
    const int whalf = tid & 1;     // 32-col half

    // ldmatrix lane addressing
    const int g  = lane >> 2, tq = lane & 3;
    const int a_row = (lane & 7) + ((lane >> 3) & 1) * 8;
    const int a_col = ((lane >> 4) & 1) * 8;
    const int b_row = (lane & 7) + ((lane >> 4) & 1) * 8;
    const int b_col = ((lane >> 3) & 1) * 8;

    float acc[2][8][4];
    #pragma unroll
    for (int mi = 0; mi < 2; mi++)
        #pragma unroll
        for (int ni = 0; ni < 8; ni++)
            #pragma unroll
            for (int q = 0; q < 4; q++) acc[mi][ni][q] = 0.f;

    const float* asrc = enc + ((size_t)b * T_ + t0 + arow) * ENC_ + aq * 16;
    const __nv_bfloat16* whsrc = g_Whi + (size_t)wrow * ENC_ + whalf * 32;
    const __nv_bfloat16* wlsrc = g_Wlo + (size_t)wrow * ENC_ + whalf * 32;

    float4 av[4];   // A prefetch (16 floats)
    float  pv[8];   // prev prefetch for conv chunk

    auto loadW = [&](int s, int kc) {
        uint32_t dh = smb + s * STAGE_B + W_HI + wrow * ROWB + whalf * 64;
        uint32_t dl = smb + s * STAGE_B + W_LO + wrow * ROWB + whalf * 64;
        #pragma unroll
        for (int j = 0; j < 4; j++) {
            cp16(dh + j * 16, whsrc + kc + j * 8);
            cp16(dl + j * 16, wlsrc + kc + j * 8);
        }
    };
    auto loadA = [&](int kc) {
        #pragma unroll
        for (int j = 0; j < 4; j++) av[j] = *(const float4*)(asrc + kc + j * 4);
    };
    auto storeA = [&](int s) {
        uint32_t hi[8], lo[8];
        #pragma unroll
        for (int j = 0; j < 4; j++) {
            cvt2(av[j].x, av[j].y, hi[2*j],   lo[2*j]);
            cvt2(av[j].z, av[j].w, hi[2*j+1], lo[2*j+1]);
        }
        char* dh = sm + s * STAGE_B + A_HI + arow * ROWB + aq * 32;
        char* dl = sm + s * STAGE_B + A_LO + arow * ROWB + aq * 32;
        *(uint4*)(dh)      = make_uint4(hi[0], hi[1], hi[2], hi[3]);
        *(uint4*)(dh + 16) = make_uint4(hi[4], hi[5], hi[6], hi[7]);
        *(uint4*)(dl)      = make_uint4(lo[0], lo[1], lo[2], lo[3]);
        *(uint4*)(dl + 16) = make_uint4(lo[4], lo[5], lo[6], lo[7]);
    };
    auto loadF = [&](int s) {
        uint32_t dh = smb + s * STAGE_B + W_HI + wrow * ROWB + whalf * 32;
        cp16(dh,      g_F + wrow * 32 + whalf * 16);
        cp16(dh + 16, g_F + wrow * 32 + whalf * 16 + 8);
    };
    auto loadPrev = [&]() {
        #pragma unroll
        for (int e = 0; e < 8; e++) {
            int k = aq * 8 + e;
            int t = t0 + arow - PADC + k;
            pv[e] = (k < KCONV && t >= 0 && t < T_) ? prev[b * T_ + t] : 0.f;
        }
    };
    auto storePrev = [&](int s) {
        uint32_t hw[4];
        #pragma unroll
        for (int q = 0; q < 4; q++) {
            __nv_bfloat162 hp = __floats2bfloat162_rn(pv[2*q], pv[2*q+1]);
            hw[q] = *(uint32_t*)&hp;
        }
        *(uint4*)(sm + s * STAGE_B + A_HI + arow * ROWB + aq * 16)
            = make_uint4(hw[0], hw[1], hw[2], hw[3]);
    };

    auto consume = [&](int s, int ksteps, bool do_lo) {
        const uint32_t base = smb + s * STAGE_B;
        for (int ks = 0; ks < ksteps; ks++) {
            const int kb = ks * 16;
            uint32_t ahi[2][4], alo_[2][4];
            #pragma unroll
            for (int mi = 0; mi < 2; mi++)
                ldsm_x4(ahi[mi], base + A_HI + (wm * 32 + mi * 16 + a_row) * ROWB
                                 + (kb + a_col) * 2);
            if (do_lo) {
                #pragma unroll
                for (int mi = 0; mi < 2; mi++)
                    ldsm_x4(alo_[mi], base + A_LO + (wm * 32 + mi * 16 + a_row) * ROWB
                                      + (kb + a_col) * 2);
            }
            #pragma unroll
            for (int p = 0; p < 4; p++) {
                uint32_t wf[4];
                ldsm_x4(wf, base + W_HI + (wn * 64 + p * 16 + b_row) * ROWB
                            + (kb + b_col) * 2);
                #pragma unroll
                for (int mi = 0; mi < 2; mi++) {
                    mma_bf16(acc[mi][2*p][0], acc[mi][2*p][1], acc[mi][2*p][2], acc[mi][2*p][3],
                             ahi[mi][0], ahi[mi][1], ahi[mi][2], ahi[mi][3], wf[0], wf[1]);
                    mma_bf16(acc[mi][2*p+1][0], acc[mi][2*p+1][1], acc[mi][2*p+1][2], acc[mi][2*p+1][3],
                             ahi[mi][0], ahi[mi][1], ahi[mi][2], ahi[mi][3], wf[2], wf[3]);
                }
                if (do_lo) {
                    #pragma unroll
                    for (int mi = 0; mi < 2; mi++) {
                        mma_bf16(acc[mi][2*p][0], acc[mi][2*p][1], acc[mi][2*p][2], acc[mi][2*p][3],
                                 alo_[mi][0], alo_[mi][1], alo_[mi][2], alo_[mi][3], wf[0], wf[1]);
                        mma_bf16(acc[mi][2*p+1][0], acc[mi][2*p+1][1], acc[mi][2*p+1][2], acc[mi][2*p+1][3],
                                 alo_[mi][0], alo_[mi][1], alo_[mi][2], alo_[mi][3], wf[2], wf[3]);
                    }
                }
            }
            if (do_lo) {
                #pragma unroll
                for (int p = 0; p < 4; p++) {
                    uint32_t wf[4];
                    ldsm_x4(wf, base + W_LO + (wn * 64 + p * 16 + b_row) * ROWB
                                + (kb + b_col) * 2);
                    #pragma unroll
                    for (int mi = 0; mi < 2; mi++) {
                        mma_bf16(acc[mi][2*p][0], acc[mi][2*p][1], acc[mi][2*p][2], acc[mi][2*p][3],
                                 ahi[mi][0], ahi[mi][1], ahi[mi][2], ahi[mi][3], wf[0], wf[1]);
                        mma_bf16(acc[mi][2*p+1][0], acc[mi][2*p+1][1], acc[mi][2*p+1][2], acc[mi][2*p+1][3],
                                 ahi[mi][0], ahi[mi][1], ahi[mi][2], ahi[mi][3], wf[2], wf[3]);
                    }
                }
            }
        }
    };

    // ---- prologue: chunk 0 ----
    loadW(0, 0);
    CP_COMMIT();
    loadA(0);
    storeA(0);
    CP_WAIT0();
    __syncthreads();

    // ---- main loop: chunks 0..7 = GEMM, chunk 8 = conv ----
    for (int c = 0; c <= 8; c++) {
        const int cur = c & 1, nxt = cur ^ 1;
        if (c < 7) {
            loadW(nxt, (c + 1) * 64);
            CP_COMMIT();
            loadA((c + 1) * 64);
        } else if (c == 7) {
            loadF(nxt);
            CP_COMMIT();
            loadPrev();
        }
        if (c < 8) consume(cur, 4, true);
        else       consume(cur, 2, false);
        if (c < 7) {
            storeA(nxt);
            CP_WAIT0();
        } else if (c == 7) {
            storePrev(nxt);
            CP_WAIT0();
        }
        __syncthreads();
    }

    // ---- epilogue: energy[row] = sum_h w_w[h]*tanh(acc + dec) ----
    float* red = (float*)sm;   // 128 x 4 floats (aliases stage0, post-sync)
    float wv[16], dv[16];
    {
        int cbase = wn * 64 + tq * 2;
        #pragma unroll
        for (int ni = 0; ni < 8; ni++) {
            int n = cbase + ni * 8;
            wv[2 * ni]     = w_w[n];
            wv[2 * ni + 1] = w_w[n + 1];
            dv[2 * ni]     = g_dec[b * HID_ + n];
            dv[2 * ni + 1] = g_dec[b * HID_ + n + 1];
        }
    }
    #pragma unroll
    for (int mi = 0; mi < 2; mi++) {
        #pragma unroll
        for (int h2 = 0; h2 < 2; h2++) {
            float p = 0.f;
            #pragma unroll
            for (int ni = 0; ni < 8; ni++) {
                #pragma unroll
                for (int j = 0; j < 2; j++) {
                    float s = acc[mi][ni][h2 * 2 + j] + dv[2 * ni + j];
                    p += wv[2 * ni + j] * tanhf(s);
                }
            }
            p += __shfl_xor_sync(0xffffffffu, p, 1);
            p += __shfl_xor_sync(0xffffffffu, p, 2);
            if (tq == 0) {
                int row = wm * 32 + mi * 16 + h2 * 8 + g;
                red[row * 4 + wn] = p;
            }
        }
    }
    __syncthreads();
    if (tid < 128) {
        g_energy[m0 + tid] = red[tid * 4] + red[tid * 4 + 1]
                           + red[tid * 4 + 2] + red[tid * 4 + 3];
    }
}

// ---------------- masked softmax over T ----------------
__global__ void softmax_kernel(const int* __restrict__ text_len, float* __restrict__ out) {
    __shared__ float sh[T_];
    __shared__ float rbuf[256];
    int b = blockIdx.x, tid = threadIdx.x;
    int len = text_len[b];

    float mx = -INFINITY;
    for (int t = tid; t < T_; t += 256) {
        float v = (t < len) ? g_energy[b * T_ + t] : -INFINITY;
        sh[t] = v;
        mx = fmaxf(mx, v);
    }
    rbuf[tid] = mx; __syncthreads();
    for (int s = 128; s > 0; s >>= 1) {
        if (tid < s) rbuf[tid] = fmaxf(rbuf[tid], rbuf[tid + s]);
        __syncthreads();
    }
    mx = rbuf[0];
    __syncthreads();

    float sum = 0.f;
    for (int t = tid; t < T_; t += 256) {
        float v = sh[t];
        float e = (v == -INFINITY) ? 0.f : expf(v - mx);
        sh[t] = e;
        sum += e;
    }
    rbuf[tid] = sum; __syncthreads();
    for (int s = 128; s > 0; s >>= 1) {
        if (tid < s) rbuf[tid] += rbuf[tid + s];
        __syncthreads();
    }
    float inv = 1.f / rbuf[0];

    float* attw = out + B_ * ENC_;
    for (int t = tid; t < T_; t += 256)
        attw[b * T_ + t] = sh[t] * inv;
}

// ---------------- att_c = sum_t att_w[b,t] * enc[b,t,:]  (16 t-slices) ----------------
__global__ void attc_part(const float* __restrict__ enc, const float* __restrict__ attw) {
    __shared__ float w[128];
    int ts = blockIdx.x;
    int b  = blockIdx.y;
    int tid = threadIdx.x;  // 128
    w[tid] = attw[b * T_ + ts * 128 + tid];
    __syncthreads();

    const float4* e4 = (const float4*)(enc + ((size_t)b * T_ + ts * 128) * ENC_) + tid;
    float ax = 0.f, ay = 0.f, az = 0.f, aw = 0.f;
    #pragma unroll 8
    for (int tt = 0; tt < 128; tt++) {
        float4 v = e4[(size_t)tt * (ENC_ / 4)];
        float ww = w[tt];
        ax += ww * v.x; ay += ww * v.y; az += ww * v.z; aw += ww * v.w;
    }
    float4 rr; rr.x = ax; rr.y = ay; rr.z = az; rr.w = aw;
    *(float4*)&g_part[((b * 16 + ts) * ENC_) + tid * 4] = rr;
}

__global__ void attc_reduce(float* __restrict__ out) {
    int i = blockIdx.x * 256 + threadIdx.x;
    if (i < B_ * ENC_) {
        int b = i >> 9, c = i & (ENC_ - 1);
        float s = 0.f;
        #pragma unroll
        for (int ts = 0; ts < 16; ts++) s += g_part[(b * 16 + ts) * ENC_ + c];
        out[i] = s;
    }
}

// ---------------- launch ----------------
extern "C" void kernel_launch(void* const* d_in, const int* in_sizes, int n_in,
                              void* d_out, int out_size) {
    const float* enc       = (const float*)d_in[0];
    const float* dec_state = (const float*)d_in[1];
    const float* prev      = (const float*)d_in[2];
    const int*   text_len  = (const int*)d_in[3];
    const float* W_enc     = (const float*)d_in[4];
    const float* b_enc     = (const float*)d_in[5];
    const float* W_dec     = (const float*)d_in[6];
    const float* W_att     = (const float*)d_in[7];
    const float* conv_w    = (const float*)d_in[8];
    const float* w_w       = (const float*)d_in[9];
    // d_in[10] = w_b: additive constant cancels in softmax.
    float* out = (float*)d_out;

    cudaFuncSetAttribute(energy_kernel, cudaFuncAttributeMaxDynamicSharedMemorySize, ESMEM);

    prep_all<<<2592, 256>>>(W_enc, W_att, conv_w, dec_state, W_dec, b_enc);

    energy_kernel<<<B_ * T_ / 128, 512, ESMEM>>>(enc, prev, w_w);

    softmax_kernel<<<B_, 256>>>(text_len, out);

    attc_part<<<dim3(16, B_), 128>>>(enc, out + B_ * ENC_);
    attc_reduce<<<(B_ * ENC_ + 255) / 256, 256>>>(out);
}

// round 8
// speedup vs baseline: 2.3282x; 1.8091x over previous
#include <cuda_runtime.h>
#include <cuda_fp16.h>
#include <math.h>
#include <stdint.h>

// Problem constants
#define B_    64
#define T_    2048
#define ENC_  512
#define DEC_  1024
#define HID_  256
#define KCONV 31
#define PADC  15

// Tiling: CTA = 128 (bt) x 256 (h), 512 threads, K-chunk 64, double-buffered
// stage (bytes): A[128*144] | W[256*144]   (fp16, 72 elems/row = 64 + 8 pad)
#define A_OFF 0
#define W_OFF 18432
#define ROWB  144
#define STAGE_B 55296
#define ESMEM (2 * STAGE_B)       // 110592

// ---------------- device scratch ----------------
__device__ __half g_Wh[HID_ * ENC_];            // W_enc in fp16
__device__ __half g_F[HID_ * 32];               // fused conv filter, col 31 = 0
__device__ float g_dec[B_ * HID_];              // dec projection + b_enc
__device__ float g_energy[B_ * T_];
__device__ float g_part[B_ * 16 * ENC_];        // att_c partials (16 t-slices)

// ---------------- PTX helpers ----------------
__device__ __forceinline__ void cp16(uint32_t dst, const void* src) {
    asm volatile("cp.async.cg.shared.global [%0], [%1], 16;\n" :: "r"(dst), "l"(src));
}
#define CP_COMMIT() asm volatile("cp.async.commit_group;\n" ::: "memory")
#define CP_WAIT0()  asm volatile("cp.async.wait_group 0;\n" ::: "memory")

__device__ __forceinline__ void ldsm_x4(uint32_t (&r)[4], uint32_t addr) {
    asm volatile("ldmatrix.sync.aligned.m8n8.x4.shared.b16 {%0,%1,%2,%3}, [%4];"
                 : "=r"(r[0]), "=r"(r[1]), "=r"(r[2]), "=r"(r[3]) : "r"(addr));
}

__device__ __forceinline__ void mma_f16(float& c0, float& c1, float& c2, float& c3,
                                        uint32_t a0, uint32_t a1, uint32_t a2, uint32_t a3,
                                        uint32_t b0, uint32_t b1) {
    asm volatile(
        "mma.sync.aligned.m16n8k16.row.col.f32.f16.f16.f32 "
        "{%0,%1,%2,%3}, {%4,%5,%6,%7}, {%8,%9}, {%0,%1,%2,%3};"
        : "+f"(c0), "+f"(c1), "+f"(c2), "+f"(c3)
        : "r"(a0), "r"(a1), "r"(a2), "r"(a3), "r"(b0), "r"(b1));
}

// ---------------- merged prep kernel ----------------
__global__ void prep_all(const float* __restrict__ W_enc,
                         const float* __restrict__ W_att,
                         const float* __restrict__ conv_w,
                         const float* __restrict__ dec_state,
                         const float* __restrict__ W_dec,
                         const float* __restrict__ b_enc) {
    int bx = blockIdx.x, tid = threadIdx.x;
    if (bx < 512) {
        int i = bx * 256 + tid;
        g_Wh[i] = __float2half_rn(W_enc[i]);
    } else if (bx < 544) {
        int i = (bx - 512) * 256 + tid;
        int h = i >> 5, k = i & 31;
        float s = 0.f;
        if (k < KCONV) {
            #pragma unroll
            for (int c = 0; c < 32; c++) s += W_att[h * 32 + c] * conv_w[c * KCONV + k];
        }
        g_F[i] = __float2half_rn(s);
    } else {
        int wid_g = (bx - 544) * 8 + (tid >> 5);
        int lane = tid & 31;
        int b = wid_g >> 8, h = wid_g & 255;
        const float4* d = (const float4*)(dec_state + (size_t)b * DEC_);
        const float4* w = (const float4*)(W_dec + (size_t)h * DEC_);
        float s = 0.f;
        #pragma unroll
        for (int it = 0; it < 8; it++) {
            float4 dv = d[lane + it * 32];
            float4 wv = w[lane + it * 32];
            s += dv.x * wv.x + dv.y * wv.y + dv.z * wv.z + dv.w * wv.w;
        }
        #pragma unroll
        for (int off = 16; off > 0; off >>= 1) s += __shfl_xor_sync(0xffffffffu, s, off);
        if (lane == 0) g_dec[wid_g] = s + b_enc[h];
    }
}

// ---------------- energy kernel: single-pass fp16 ----------------
__global__ void __launch_bounds__(512)
energy_kernel(const float* __restrict__ enc,
              const float* __restrict__ prev,
              const float* __restrict__ w_w) {
    extern __shared__ char sm[];
    uint32_t smb;
    asm("{ .reg .u64 t; cvta.to.shared.u64 t, %1; cvt.u32.u64 %0, t; }"
        : "=r"(smb) : "l"(sm));

    const int tid  = threadIdx.x;
    const int lane = tid & 31;
    const int warp = tid >> 5;
    const int wm   = warp & 3;     // rows [wm*32, +32)
    const int wn   = warp >> 2;    // cols [wn*64, +64)

    const int m0 = blockIdx.x * 128;
    const int b  = m0 >> 11;
    const int t0 = m0 & (T_ - 1);

    // producer roles
    const int arow  = tid >> 2;    // 0..127 (A row)
    const int aq    = tid & 3;     // 16-col group
    const int wrow  = tid >> 1;    // 0..255 (W row)
    const int whalf = tid & 1;     // 32-col half

    // ldmatrix lane addressing
    const int g  = lane >> 2, tq = lane & 3;
    const int a_row = (lane & 7) + ((lane >> 3) & 1) * 8;
    const int a_col = ((lane >> 4) & 1) * 8;
    const int b_row = (lane & 7) + ((lane >> 4) & 1) * 8;
    const int b_col = ((lane >> 3) & 1) * 8;

    float acc[2][8][4];
    #pragma unroll
    for (int mi = 0; mi < 2; mi++)
        #pragma unroll
        for (int ni = 0; ni < 8; ni++)
            #pragma unroll
            for (int q = 0; q < 4; q++) acc[mi][ni][q] = 0.f;

    const float* asrc = enc + ((size_t)b * T_ + t0 + arow) * ENC_ + aq * 16;
    const __half* wsrc = g_Wh + (size_t)wrow * ENC_ + whalf * 32;

    float4 av[4];   // A prefetch (16 floats)
    float  pv[8];   // prev prefetch for conv chunk

    auto loadW = [&](int s, int kc) {
        uint32_t dw = smb + s * STAGE_B + W_OFF + wrow * ROWB + whalf * 64;
        #pragma unroll
        for (int j = 0; j < 4; j++) cp16(dw + j * 16, wsrc + kc + j * 8);
    };
    auto loadA = [&](int kc) {
        #pragma unroll
        for (int j = 0; j < 4; j++) av[j] = *(const float4*)(asrc + kc + j * 4);
    };
    auto storeA = [&](int s) {
        uint32_t hv[8];
        #pragma unroll
        for (int j = 0; j < 4; j++) {
            __half2 p0 = __floats2half2_rn(av[j].x, av[j].y);
            __half2 p1 = __floats2half2_rn(av[j].z, av[j].w);
            hv[2*j]   = *(uint32_t*)&p0;
            hv[2*j+1] = *(uint32_t*)&p1;
        }
        char* da = sm + s * STAGE_B + A_OFF + arow * ROWB + aq * 32;
        *(uint4*)(da)      = make_uint4(hv[0], hv[1], hv[2], hv[3]);
        *(uint4*)(da + 16) = make_uint4(hv[4], hv[5], hv[6], hv[7]);
    };
    auto loadF = [&](int s) {
        uint32_t dw = smb + s * STAGE_B + W_OFF + wrow * ROWB + whalf * 32;
        cp16(dw,      g_F + wrow * 32 + whalf * 16);
        cp16(dw + 16, g_F + wrow * 32 + whalf * 16 + 8);
    };
    auto loadPrev = [&]() {
        #pragma unroll
        for (int e = 0; e < 8; e++) {
            int k = aq * 8 + e;
            int t = t0 + arow - PADC + k;
            pv[e] = (k < KCONV && t >= 0 && t < T_) ? prev[b * T_ + t] : 0.f;
        }
    };
    auto storePrev = [&](int s) {
        uint32_t hw[4];
        #pragma unroll
        for (int q = 0; q < 4; q++) {
            __half2 hp = __floats2half2_rn(pv[2*q], pv[2*q+1]);
            hw[q] = *(uint32_t*)&hp;
        }
        *(uint4*)(sm + s * STAGE_B + A_OFF + arow * ROWB + aq * 16)
            = make_uint4(hw[0], hw[1], hw[2], hw[3]);
    };

    auto consume = [&](int s, int ksteps) {
        const uint32_t base = smb + s * STAGE_B;
        for (int ks = 0; ks < ksteps; ks++) {
            const int kb = ks * 16;
            uint32_t af[2][4];
            #pragma unroll
            for (int mi = 0; mi < 2; mi++)
                ldsm_x4(af[mi], base + A_OFF + (wm * 32 + mi * 16 + a_row) * ROWB
                                + (kb + a_col) * 2);
            #pragma unroll
            for (int p = 0; p < 4; p++) {
                uint32_t wf[4];
                ldsm_x4(wf, base + W_OFF + (wn * 64 + p * 16 + b_row) * ROWB
                            + (kb + b_col) * 2);
                #pragma unroll
                for (int mi = 0; mi < 2; mi++) {
                    mma_f16(acc[mi][2*p][0], acc[mi][2*p][1], acc[mi][2*p][2], acc[mi][2*p][3],
                            af[mi][0], af[mi][1], af[mi][2], af[mi][3], wf[0], wf[1]);
                    mma_f16(acc[mi][2*p+1][0], acc[mi][2*p+1][1], acc[mi][2*p+1][2], acc[mi][2*p+1][3],
                            af[mi][0], af[mi][1], af[mi][2], af[mi][3], wf[2], wf[3]);
                }
            }
        }
    };

    // ---- prologue: chunk 0 ----
    loadW(0, 0);
    CP_COMMIT();
    loadA(0);
    storeA(0);
    CP_WAIT0();
    __syncthreads();

    // ---- main loop: chunks 0..7 = GEMM, chunk 8 = conv ----
    for (int c = 0; c <= 8; c++) {
        const int cur = c & 1, nxt = cur ^ 1;
        if (c < 7) {
            loadW(nxt, (c + 1) * 64);
            CP_COMMIT();
            loadA((c + 1) * 64);
        } else if (c == 7) {
            loadF(nxt);
            CP_COMMIT();
            loadPrev();
        }
        if (c < 8) consume(cur, 4);
        else       consume(cur, 2);
        if (c < 7) {
            storeA(nxt);
            CP_WAIT0();
        } else if (c == 7) {
            storePrev(nxt);
            CP_WAIT0();
        }
        __syncthreads();
    }

    // ---- epilogue: energy[row] = sum_h w_w[h]*tanh(acc + dec) ----
    float* red = (float*)sm;   // 128 x 4 floats (aliases stage0, post-sync)
    float wv[16], dv[16];
    {
        int cbase = wn * 64 + tq * 2;
        #pragma unroll
        for (int ni = 0; ni < 8; ni++) {
            int n = cbase + ni * 8;
            wv[2 * ni]     = w_w[n];
            wv[2 * ni + 1] = w_w[n + 1];
            dv[2 * ni]     = g_dec[b * HID_ + n];
            dv[2 * ni + 1] = g_dec[b * HID_ + n + 1];
        }
    }
    #pragma unroll
    for (int mi = 0; mi < 2; mi++) {
        #pragma unroll
        for (int h2 = 0; h2 < 2; h2++) {
            float p = 0.f;
            #pragma unroll
            for (int ni = 0; ni < 8; ni++) {
                #pragma unroll
                for (int j = 0; j < 2; j++) {
                    float s = acc[mi][ni][h2 * 2 + j] + dv[2 * ni + j];
                    p += wv[2 * ni + j] * tanhf(s);
                }
            }
            p += __shfl_xor_sync(0xffffffffu, p, 1);
            p += __shfl_xor_sync(0xffffffffu, p, 2);
            if (tq == 0) {
                int row = wm * 32 + mi * 16 + h2 * 8 + g;
                red[row * 4 + wn] = p;
            }
        }
    }
    __syncthreads();
    if (tid < 128) {
        g_energy[m0 + tid] = red[tid * 4] + red[tid * 4 + 1]
                           + red[tid * 4 + 2] + red[tid * 4 + 3];
    }
}

// ---------------- masked softmax over T ----------------
__global__ void softmax_kernel(const int* __restrict__ text_len, float* __restrict__ out) {
    __shared__ float sh[T_];
    __shared__ float rbuf[256];
    int b = blockIdx.x, tid = threadIdx.x;
    int len = text_len[b];

    float mx = -INFINITY;
    for (int t = tid; t < T_; t += 256) {
        float v = (t < len) ? g_energy[b * T_ + t] : -INFINITY;
        sh[t] = v;
        mx = fmaxf(mx, v);
    }
    rbuf[tid] = mx; __syncthreads();
    for (int s = 128; s > 0; s >>= 1) {
        if (tid < s) rbuf[tid] = fmaxf(rbuf[tid], rbuf[tid + s]);
        __syncthreads();
    }
    mx = rbuf[0];
    __syncthreads();

    float sum = 0.f;
    for (int t = tid; t < T_; t += 256) {
        float v = sh[t];
        float e = (v == -INFINITY) ? 0.f : expf(v - mx);
        sh[t] = e;
        sum += e;
    }
    rbuf[tid] = sum; __syncthreads();
    for (int s = 128; s > 0; s >>= 1) {
        if (tid < s) rbuf[tid] += rbuf[tid + s];
        __syncthreads();
    }
    float inv = 1.f / rbuf[0];

    float* attw = out + B_ * ENC_;
    for (int t = tid; t < T_; t += 256)
        attw[b * T_ + t] = sh[t] * inv;
}

// ---------------- att_c = sum_t att_w[b,t] * enc[b,t,:]  (16 t-slices) ----------------
__global__ void attc_part(const float* __restrict__ enc, const float* __restrict__ attw) {
    __shared__ float w[128];
    int ts = blockIdx.x;
    int b  = blockIdx.y;
    int tid = threadIdx.x;  // 128
    w[tid] = attw[b * T_ + ts * 128 + tid];
    __syncthreads();

    const float4* e4 = (const float4*)(enc + ((size_t)b * T_ + ts * 128) * ENC_) + tid;
    float ax = 0.f, ay = 0.f, az = 0.f, aw = 0.f;
    #pragma unroll 8
    for (int tt = 0; tt < 128; tt++) {
        float4 v = e4[(size_t)tt * (ENC_ / 4)];
        float ww = w[tt];
        ax += ww * v.x; ay += ww * v.y; az += ww * v.z; aw += ww * v.w;
    }
    float4 rr; rr.x = ax; rr.y = ay; rr.z = az; rr.w = aw;
    *(float4*)&g_part[((b * 16 + ts) * ENC_) + tid * 4] = rr;
}

__global__ void attc_reduce(float* __restrict__ out) {
    int i = blockIdx.x * 256 + threadIdx.x;
    if (i < B_ * ENC_) {
        int b = i >> 9, c = i & (ENC_ - 1);
        float s = 0.f;
        #pragma unroll
        for (int ts = 0; ts < 16; ts++) s += g_part[(b * 16 + ts) * ENC_ + c];
        out[i] = s;
    }
}

// ---------------- launch ----------------
extern "C" void kernel_launch(void* const* d_in, const int* in_sizes, int n_in,
                              void* d_out, int out_size) {
    const float* enc       = (const float*)d_in[0];
    const float* dec_state = (const float*)d_in[1];
    const float* prev      = (const float*)d_in[2];
    const int*   text_len  = (const int*)d_in[3];
    const float* W_enc     = (const float*)d_in[4];
    const float* b_enc     = (const float*)d_in[5];
    const float* W_dec     = (const float*)d_in[6];
    const float* W_att     = (const float*)d_in[7];
    const float* conv_w    = (const float*)d_in[8];
    const float* w_w       = (const float*)d_in[9];
    // d_in[10] = w_b: additive constant cancels in softmax.
    float* out = (float*)d_out;

    cudaFuncSetAttribute(energy_kernel, cudaFuncAttributeMaxDynamicSharedMemorySize, ESMEM);

    prep_all<<<2592, 256>>>(W_enc, W_att, conv_w, dec_state, W_dec, b_enc);

    energy_kernel<<<B_ * T_ / 128, 512, ESMEM>>>(enc, prev, w_w);

    softmax_kernel<<<B_, 256>>>(text_len, out);

    attc_part<<<dim3(16, B_), 128>>>(enc, out + B_ * ENC_);
    attc_reduce<<<(B_ * ENC_ + 255) / 256, 256>>>(out);
}